// round 1
// baseline (speedup 1.0000x reference)
#include <cuda_runtime.h>

// Problem constants
#define BB 8
#define SS 1024
#define EE 128
#define HH 8
#define DD 128

// Scratch (static device globals -- no runtime allocation allowed)
__device__ float g_Q[(size_t)BB*HH*SS*DD];   // [B,H,S,D]
__device__ float g_K[(size_t)BB*HH*SS*DD];
__device__ float g_V[(size_t)BB*HH*SS*DD];
__device__ float g_O[(size_t)BB*SS*HH*DD];   // [B,S,H*D] row-major (concat layout)

// ---------------------------------------------------------------------------
// Fused QKV projection: out[m][n] = sum_k X[m][k] * W[n][k]
// M=8192 (B*S), N=1024 (H*D), K=128. blockIdx.z selects {q,k,v}.
// Writes directly into [B,H,S,D] layout.
// ---------------------------------------------------------------------------
__global__ __launch_bounds__(256) void qkv_proj_kernel(
    const float* __restrict__ q, const float* __restrict__ k, const float* __restrict__ v,
    const float* __restrict__ Wq, const float* __restrict__ Wk, const float* __restrict__ Wv)
{
    __shared__ float As[16*128];   // As[kk][m]
    __shared__ float Bs[16*128];   // Bs[kk][n]

    const float* A; const float* W; float* O;
    if (blockIdx.z == 0)      { A = q; W = Wq; O = g_Q; }
    else if (blockIdx.z == 1) { A = k; W = Wk; O = g_K; }
    else                      { A = v; W = Wv; O = g_V; }

    const int m0 = blockIdx.y * 128;
    const int h  = blockIdx.x;            // head == N-tile (128 cols per head)
    const int tid = threadIdx.x;
    const int ty = tid >> 4, tx = tid & 15;

    float acc[8][8];
    #pragma unroll
    for (int i = 0; i < 8; i++)
        #pragma unroll
        for (int j = 0; j < 8; j++) acc[i][j] = 0.f;

    for (int kc = 0; kc < 128; kc += 16) {
        #pragma unroll
        for (int q2 = 0; q2 < 2; q2++) {
            int fid = tid*2 + q2;
            int m  = fid >> 2;
            int kk = (fid & 3) << 2;
            float4 fa = *(const float4*)(A + (size_t)(m0+m)*128 + kc + kk);
            As[(kk+0)*128+m] = fa.x; As[(kk+1)*128+m] = fa.y;
            As[(kk+2)*128+m] = fa.z; As[(kk+3)*128+m] = fa.w;
            float4 fb = *(const float4*)(W + (size_t)(h*128+m)*128 + kc + kk);
            Bs[(kk+0)*128+m] = fb.x; Bs[(kk+1)*128+m] = fb.y;
            Bs[(kk+2)*128+m] = fb.z; Bs[(kk+3)*128+m] = fb.w;
        }
        __syncthreads();
        #pragma unroll
        for (int kk = 0; kk < 16; kk++) {
            float4 a0 = *(const float4*)&As[kk*128 + ty*8];
            float4 a1 = *(const float4*)&As[kk*128 + ty*8 + 4];
            float4 b0 = *(const float4*)&Bs[kk*128 + tx*8];
            float4 b1 = *(const float4*)&Bs[kk*128 + tx*8 + 4];
            float a_[8] = {a0.x,a0.y,a0.z,a0.w,a1.x,a1.y,a1.z,a1.w};
            float b_[8] = {b0.x,b0.y,b0.z,b0.w,b1.x,b1.y,b1.z,b1.w};
            #pragma unroll
            for (int i = 0; i < 8; i++)
                #pragma unroll
                for (int j = 0; j < 8; j++)
                    acc[i][j] += a_[i]*b_[j];
        }
        __syncthreads();
    }

    #pragma unroll
    for (int i = 0; i < 8; i++) {
        int m = m0 + ty*8 + i;
        int b_ = m >> 10, s_ = m & 1023;
        float* op = O + (((size_t)(b_*HH + h))*SS + s_)*DD + tx*8;
        *(float4*)op     = make_float4(acc[i][0],acc[i][1],acc[i][2],acc[i][3]);
        *(float4*)(op+4) = make_float4(acc[i][4],acc[i][5],acc[i][6],acc[i][7]);
    }
}

// ---------------------------------------------------------------------------
// Flash-style attention. One block = 128 query rows of one (b,h).
// Online softmax over 16 key-blocks of 64. O accum in registers (8x8/thread).
// ---------------------------------------------------------------------------
#define QP 129   // padded Q/K row pitch (odd -> conflict-friendly strided reads)
#define PP 65    // padded score row pitch
#define BM 128
#define BN 64

__global__ __launch_bounds__(256, 1) void attn_kernel(const float* __restrict__ mask)
{
    extern __shared__ float sm[];
    float* Qs  = sm;                    // BM*QP
    float* Ks  = Qs + BM*QP;            // BN*QP
    float* Vs  = Ks + BN*QP;            // BN*DD
    float* Ps  = Vs + BN*DD;            // BM*PP
    float* m_s = Ps + BM*PP;            // BM
    float* l_s = m_s + BM;              // BM
    float* al_s = l_s + BM;             // BM

    const int tid = threadIdx.x;
    const int bh = blockIdx.y;
    const int b_ = bh >> 3;
    const int h  = bh & 7;
    const int q0 = blockIdx.x * BM;
    const float* qp = g_Q + ((size_t)bh*SS + q0)*DD;
    const float* kp = g_K + (size_t)bh*SS*DD;
    const float* vp = g_V + (size_t)bh*SS*DD;
    const float* mb = mask + b_*SS;

    for (int idx = tid; idx < BM*(DD/4); idx += 256) {
        int r = idx >> 5, c = (idx & 31) << 2;
        float4 f = *(const float4*)(qp + (size_t)r*DD + c);
        float* dst = &Qs[r*QP + c];
        dst[0] = f.x; dst[1] = f.y; dst[2] = f.z; dst[3] = f.w;
    }
    if (tid < BM) { m_s[tid] = -3.0e38f; l_s[tid] = 0.f; }

    float o[8][8];
    #pragma unroll
    for (int i = 0; i < 8; i++)
        #pragma unroll
        for (int j = 0; j < 8; j++) o[i][j] = 0.f;

    const int ty = tid >> 4, tx = tid & 15;
    __syncthreads();

    for (int j0 = 0; j0 < SS; j0 += BN) {
        // load K,V tiles
        for (int idx = tid; idx < BN*(DD/4); idx += 256) {
            int r = idx >> 5, c = (idx & 31) << 2;
            float4 f = *(const float4*)(kp + (size_t)(j0+r)*DD + c);
            float* dk = &Ks[r*QP + c];
            dk[0] = f.x; dk[1] = f.y; dk[2] = f.z; dk[3] = f.w;
            float4 g = *(const float4*)(vp + (size_t)(j0+r)*DD + c);
            *(float4*)&Vs[r*DD + c] = g;
        }
        __syncthreads();

        // S = Q K^T  : rows ty*8..+7, keys tx*4..+3
        float acc[8][4];
        #pragma unroll
        for (int i = 0; i < 8; i++)
            #pragma unroll
            for (int j = 0; j < 4; j++) acc[i][j] = 0.f;

        #pragma unroll 4
        for (int kq = 0; kq < DD; kq++) {
            float a_[8], bb[4];
            #pragma unroll
            for (int i = 0; i < 8; i++) a_[i] = Qs[(ty*8+i)*QP + kq];
            #pragma unroll
            for (int j = 0; j < 4; j++) bb[j] = Ks[(tx*4+j)*QP + kq];
            #pragma unroll
            for (int i = 0; i < 8; i++)
                #pragma unroll
                for (int j = 0; j < 4; j++)
                    acc[i][j] += a_[i]*bb[j];
        }

        const float scale = 0.08838834764831845f;  // 1/sqrt(128)
        float mv[4];
        #pragma unroll
        for (int j = 0; j < 4; j++) mv[j] = mb[j0 + tx*4 + j];
        #pragma unroll
        for (int i = 0; i < 8; i++)
            #pragma unroll
            for (int j = 0; j < 4; j++)
                Ps[(ty*8+i)*PP + tx*4+j] = acc[i][j]*scale + mv[j];
        __syncthreads();

        // online softmax (one thread per row)
        if (tid < BM) {
            int r = tid;
            float mo = m_s[r];
            float mx = mo;
            #pragma unroll 8
            for (int j = 0; j < BN; j++) mx = fmaxf(mx, Ps[r*PP+j]);
            float alpha = __expf(mo - mx);
            float sum = 0.f;
            #pragma unroll 8
            for (int j = 0; j < BN; j++) {
                float p = __expf(Ps[r*PP+j] - mx);
                Ps[r*PP+j] = p;
                sum += p;
            }
            l_s[r] = l_s[r]*alpha + sum;
            m_s[r] = mx;
            al_s[r] = alpha;
        }
        __syncthreads();

        // O = alpha*O + P V  : rows ty*8..+7, cols tx*8..+7
        float al[8];
        #pragma unroll
        for (int i = 0; i < 8; i++) al[i] = al_s[ty*8+i];
        #pragma unroll
        for (int i = 0; i < 8; i++)
            #pragma unroll
            for (int j = 0; j < 8; j++) o[i][j] *= al[i];

        #pragma unroll 4
        for (int kq = 0; kq < BN; kq++) {
            float a_[8];
            #pragma unroll
            for (int i = 0; i < 8; i++) a_[i] = Ps[(ty*8+i)*PP + kq];
            float4 b0 = *(const float4*)&Vs[kq*DD + tx*8];
            float4 b1 = *(const float4*)&Vs[kq*DD + tx*8 + 4];
            float bb[8] = {b0.x,b0.y,b0.z,b0.w,b1.x,b1.y,b1.z,b1.w};
            #pragma unroll
            for (int i = 0; i < 8; i++)
                #pragma unroll
                for (int j = 0; j < 8; j++)
                    o[i][j] += a_[i]*bb[j];
        }
        __syncthreads();
    }

    // epilogue: normalize and write to concat layout [B,S,H*D]
    #pragma unroll
    for (int i = 0; i < 8; i++) {
        int r = ty*8 + i;
        float inv = 1.f / (l_s[r] + 1e-12f);
        int s_ = q0 + r;
        float* op = g_O + ((size_t)(b_*SS + s_))*(HH*DD) + h*DD + tx*8;
        *(float4*)op     = make_float4(o[i][0]*inv, o[i][1]*inv, o[i][2]*inv, o[i][3]*inv);
        *(float4*)(op+4) = make_float4(o[i][4]*inv, o[i][5]*inv, o[i][6]*inv, o[i][7]*inv);
    }
}

// ---------------------------------------------------------------------------
// Output projection: out[m][n] = sum_k O[m][k]*Wc[n][k] + bc[n]
// M=8192, N=128, K=1024
// ---------------------------------------------------------------------------
__global__ __launch_bounds__(256) void out_proj_kernel(
    const float* __restrict__ Wc, const float* __restrict__ bc, float* __restrict__ out)
{
    __shared__ float As[16*128];
    __shared__ float Bs[16*128];

    const int m0 = blockIdx.x * 128;
    const int tid = threadIdx.x;
    const int ty = tid >> 4, tx = tid & 15;

    float acc[8][8];
    #pragma unroll
    for (int i = 0; i < 8; i++)
        #pragma unroll
        for (int j = 0; j < 8; j++) acc[i][j] = 0.f;

    for (int kc = 0; kc < 1024; kc += 16) {
        #pragma unroll
        for (int q2 = 0; q2 < 2; q2++) {
            int fid = tid*2 + q2;
            int m  = fid >> 2;
            int kk = (fid & 3) << 2;
            float4 fa = *(const float4*)(g_O + (size_t)(m0+m)*1024 + kc + kk);
            As[(kk+0)*128+m] = fa.x; As[(kk+1)*128+m] = fa.y;
            As[(kk+2)*128+m] = fa.z; As[(kk+3)*128+m] = fa.w;
            float4 fb = *(const float4*)(Wc + (size_t)m*1024 + kc + kk);
            Bs[(kk+0)*128+m] = fb.x; Bs[(kk+1)*128+m] = fb.y;
            Bs[(kk+2)*128+m] = fb.z; Bs[(kk+3)*128+m] = fb.w;
        }
        __syncthreads();
        #pragma unroll
        for (int kk = 0; kk < 16; kk++) {
            float4 a0 = *(const float4*)&As[kk*128 + ty*8];
            float4 a1 = *(const float4*)&As[kk*128 + ty*8 + 4];
            float4 b0 = *(const float4*)&Bs[kk*128 + tx*8];
            float4 b1 = *(const float4*)&Bs[kk*128 + tx*8 + 4];
            float a_[8] = {a0.x,a0.y,a0.z,a0.w,a1.x,a1.y,a1.z,a1.w};
            float b_[8] = {b0.x,b0.y,b0.z,b0.w,b1.x,b1.y,b1.z,b1.w};
            #pragma unroll
            for (int i = 0; i < 8; i++)
                #pragma unroll
                for (int j = 0; j < 8; j++)
                    acc[i][j] += a_[i]*b_[j];
        }
        __syncthreads();
    }

    float4 bb0 = *(const float4*)(bc + tx*8);
    float4 bb1 = *(const float4*)(bc + tx*8 + 4);
    #pragma unroll
    for (int i = 0; i < 8; i++) {
        int m = m0 + ty*8 + i;
        float* op = out + (size_t)m*128 + tx*8;
        *(float4*)op     = make_float4(acc[i][0]+bb0.x, acc[i][1]+bb0.y,
                                       acc[i][2]+bb0.z, acc[i][3]+bb0.w);
        *(float4*)(op+4) = make_float4(acc[i][4]+bb1.x, acc[i][5]+bb1.y,
                                       acc[i][6]+bb1.z, acc[i][7]+bb1.w);
    }
}

// ---------------------------------------------------------------------------
extern "C" void kernel_launch(void* const* d_in, const int* in_sizes, int n_in,
                              void* d_out, int out_size)
{
    const float* q    = (const float*)d_in[0];
    const float* k    = (const float*)d_in[1];
    const float* v    = (const float*)d_in[2];
    const float* mask = (const float*)d_in[3];
    const float* Wq   = (const float*)d_in[4];
    const float* Wk   = (const float*)d_in[5];
    const float* Wv   = (const float*)d_in[6];
    const float* Wc   = (const float*)d_in[7];
    const float* bc   = (const float*)d_in[8];
    float* out = (float*)d_out;

    const size_t attn_smem = (size_t)(BM*QP + BN*QP + BN*DD + BM*PP + 3*BM) * sizeof(float);
    cudaFuncSetAttribute(attn_kernel, cudaFuncAttributeMaxDynamicSharedMemorySize,
                         (int)attn_smem);

    qkv_proj_kernel<<<dim3(8, 64, 3), 256>>>(q, k, v, Wq, Wk, Wv);
    attn_kernel<<<dim3(8, 64), 256, attn_smem>>>(mask);
    out_proj_kernel<<<64, 256>>>(Wc, bc, out);
}